// round 10
// baseline (speedup 1.0000x reference)
#include <cuda_runtime.h>
#include <cuda_fp16.h>

// Guided filter, RADIUS=8, EPS=0.01, (8,3,1024,1024) fp32.
// Vertical-first separable box. CPT=4, TPB=256 (8 warps, 128-col strips).
// Horizontal box via distance-2 identity:
//   box[4k+j] = suf_{k-2}(j) + U_{k-1} + U_k + U_{k+1} + pre_{k+2}(j)
// (10 independent shfl/series); warp-edge halos via smem raw-V publish.
// kA: x,y -> (a,b) packed half2.  kB: (a,b),x -> out.

#define W     1024
#define Hh    1024
#define IMGS  24
#define HW    (Hh * W)
#define TOTAL (IMGS * HW)
#define RAD   8
#define EPSF  0.01f
#define SEGR  32
#define SEGS  (Hh / SEGR)
#define TPB   256
#define NW    8
#define FULLM 0xffffffffu

__device__ __align__(16) __half2 g_ab[TOTAL];

__device__ __forceinline__ unsigned int pack_h2(float a, float b) {
    __half2 h = __floats2half2_rn(a, b);
    return *reinterpret_cast<unsigned int*>(&h);
}
__device__ __forceinline__ void dec_h2(unsigned int u, float& a, float& b) {
    __half2 h = *reinterpret_cast<__half2*>(&u);
    float2 f = __half22float2(h);
    a = f.x; b = f.y;
}

// 17-wide horizontal box of per-lane vertical sums V[4].
// Halo float4s: L30/L31 = left warp's lanes 30/31 V; R0/R1 = right warp's
// lanes 0/1 V. hasL/hasR false at image edges (zero-pad).
__device__ __forceinline__ void box4(const float V[4],
                                     const float4& L30, const float4& L31,
                                     const float4& R0,  const float4& R1,
                                     bool hasL, bool hasR, int lane,
                                     float bx[4]) {
    float pre[4];
    pre[0] = V[0]; pre[1] = pre[0] + V[1];
    pre[2] = pre[1] + V[2]; pre[3] = pre[2] + V[3];
    float U = pre[3];
    float suf[4];
    suf[0] = U; suf[1] = U - pre[0]; suf[2] = U - pre[1]; suf[3] = U - pre[2];

    float s2[4], p2[4];
    #pragma unroll
    for (int j = 0; j < 4; j++) s2[j] = __shfl_up_sync(FULLM, suf[j], 2);
    #pragma unroll
    for (int j = 0; j < 4; j++) p2[j] = __shfl_down_sync(FULLM, pre[j], 2);
    float Ul = __shfl_up_sync(FULLM, U, 1);
    float Ur = __shfl_down_sync(FULLM, U, 1);

    if (lane == 0) {
        s2[0] = hasL ? (L30.x + L30.y + L30.z + L30.w) : 0.f;
        s2[1] = hasL ? (L30.y + L30.z + L30.w) : 0.f;
        s2[2] = hasL ? (L30.z + L30.w) : 0.f;
        s2[3] = hasL ? (L30.w) : 0.f;
        Ul    = hasL ? (L31.x + L31.y + L31.z + L31.w) : 0.f;
    } else if (lane == 1) {
        s2[0] = hasL ? (L31.x + L31.y + L31.z + L31.w) : 0.f;
        s2[1] = hasL ? (L31.y + L31.z + L31.w) : 0.f;
        s2[2] = hasL ? (L31.z + L31.w) : 0.f;
        s2[3] = hasL ? (L31.w) : 0.f;
    }
    if (lane == 31) {
        p2[0] = hasR ? (R1.x) : 0.f;
        p2[1] = hasR ? (R1.x + R1.y) : 0.f;
        p2[2] = hasR ? (R1.x + R1.y + R1.z) : 0.f;
        p2[3] = hasR ? (R1.x + R1.y + R1.z + R1.w) : 0.f;
        Ur    = hasR ? (R0.x + R0.y + R0.z + R0.w) : 0.f;
    } else if (lane == 30) {
        p2[0] = hasR ? (R0.x) : 0.f;
        p2[1] = hasR ? (R0.x + R0.y) : 0.f;
        p2[2] = hasR ? (R0.x + R0.y + R0.z) : 0.f;
        p2[3] = hasR ? (R0.x + R0.y + R0.z + R0.w) : 0.f;
    }

    float mid = (Ul + U) + Ur;
    #pragma unroll
    for (int j = 0; j < 4; j++) bx[j] = (s2[j] + mid) + p2[j];
}

// publish edge-lane V into smem slot [which][ser]: which 0=l0,1=l1,2=l30,3=l31
template<int NSER>
__device__ __forceinline__ void pub_edges(float4* smw, int lane,
                                          const float V[][4]) {
    int which = -1;
    if (lane == 0) which = 0;
    else if (lane == 1) which = 1;
    else if (lane == 30) which = 2;
    else if (lane == 31) which = 3;
    if (which >= 0) {
        #pragma unroll
        for (int s = 0; s < NSER; s++)
            smw[which * NSER + s] = make_float4(V[s][0], V[s][1], V[s][2], V[s][3]);
    }
}

template<int SGN>
__device__ __forceinline__ void addA(const float* __restrict__ xr,
                                     const float* __restrict__ yr, int col0,
                                     float V[4][4]) {
    float4 a = *(const float4*)(xr + col0);
    float4 b = *(const float4*)(yr + col0);
    float xv[4] = {a.x, a.y, a.z, a.w};
    float yv[4] = {b.x, b.y, b.z, b.w};
    #pragma unroll
    for (int j = 0; j < 4; j++) {
        if (SGN > 0) {
            V[0][j] += xv[j];
            V[1][j] += yv[j];
            V[2][j] = fmaf(xv[j], xv[j], V[2][j]);
            V[3][j] = fmaf(xv[j], yv[j], V[3][j]);
        } else {
            V[0][j] -= xv[j];
            V[1][j] -= yv[j];
            V[2][j] = fmaf(-xv[j], xv[j], V[2][j]);
            V[3][j] = fmaf(-xv[j], yv[j], V[3][j]);
        }
    }
}

template<int SGN>
__device__ __forceinline__ void addB(const __half2* __restrict__ abr, int col0,
                                     float V[2][4]) {
    uint4 p = *(const uint4*)(abr + col0);
    unsigned int u[4] = {p.x, p.y, p.z, p.w};
    #pragma unroll
    for (int j = 0; j < 4; j++) {
        float a, b; dec_h2(u[j], a, b);
        if (SGN > 0) { V[0][j] += a; V[1][j] += b; }
        else         { V[0][j] -= a; V[1][j] -= b; }
    }
}

// ---------------------------------------------------------------------------
__global__ void __launch_bounds__(TPB) kA(const float* __restrict__ x,
                                          const float* __restrict__ y) {
    __shared__ __align__(16) float4 sm[2][NW][4 * 4];   // [par][warp][which*NSER+ser]
    int img  = blockIdx.y;
    int s    = blockIdx.x * SEGR;
    int warp = threadIdx.x >> 5;
    int lane = threadIdx.x & 31;
    int col0 = (warp << 7) + lane * 4;
    const float* xb = x + img * HW;
    const float* yb = y + img * HW;
    bool hasL = (warp > 0), hasR = (warp < NW - 1);
    int wl = hasL ? warp - 1 : 0;
    int wr = hasR ? warp + 1 : NW - 1;

    float V[4][4];
    #pragma unroll
    for (int ser = 0; ser < 4; ser++)
        #pragma unroll
        for (int j = 0; j < 4; j++) V[ser][j] = 0.f;

    for (int r = max(0, s - RAD); r <= s + RAD; r++)
        addA<+1>(xb + r * W, yb + r * W, col0, V);

    float inv_nx[4];
    #pragma unroll
    for (int j = 0; j < 4; j++) {
        int c = col0 + j;
        inv_nx[j] = __frcp_rn((float)(min(W - 1, c + RAD) - max(0, c - RAD) + 1));
    }

    __half2* gab = g_ab + img * HW;

    for (int o = s; o < s + SEGR; o++) {
        int par = o & 1;
        pub_edges<4>(&sm[par][warp][0], lane, V);
        __syncthreads();

        float bx[4][4];
        #pragma unroll
        for (int ser = 0; ser < 4; ser++) {
            float4 L30 = sm[par][wl][2 * 4 + ser];
            float4 L31 = sm[par][wl][3 * 4 + ser];
            float4 R0  = sm[par][wr][0 * 4 + ser];
            float4 R1  = sm[par][wr][1 * 4 + ser];
            box4(V[ser], L30, L31, R0, R1, hasL, hasR, lane, bx[ser]);
        }

        float inv_ny = __frcp_rn((float)(min(Hh - 1, o + RAD) - max(0, o - RAD) + 1));
        unsigned int pk[4];
        #pragma unroll
        for (int j = 0; j < 4; j++) {
            float invN = inv_nx[j] * inv_ny;
            float mx = bx[0][j] * invN, my = bx[1][j] * invN;
            float varx = fmaf(-mx, mx, bx[2][j] * invN);
            float cov  = fmaf(-mx, my, bx[3][j] * invN);
            float a = __fdividef(cov, varx + EPSF);
            float b = fmaf(-a, mx, my);
            pk[j] = pack_h2(a, b);
        }
        uint4 u;
        u.x = pk[0]; u.y = pk[1]; u.z = pk[2]; u.w = pk[3];
        *(uint4*)(gab + o * W + col0) = u;

        int lead = o + RAD + 1, trail = o - RAD;
        if (lead < Hh)
            addA<+1>(xb + lead * W, yb + lead * W, col0, V);
        if (trail >= 0)
            addA<-1>(xb + trail * W, yb + trail * W, col0, V);
    }
}

// ---------------------------------------------------------------------------
__global__ void __launch_bounds__(TPB) kB(const float* __restrict__ x,
                                          float* __restrict__ out) {
    __shared__ __align__(16) float4 sm[2][NW][4 * 2];
    int img  = blockIdx.y;
    int s    = blockIdx.x * SEGR;
    int warp = threadIdx.x >> 5;
    int lane = threadIdx.x & 31;
    int col0 = (warp << 7) + lane * 4;
    const __half2* abr = g_ab + img * HW;
    const float* xb = x + img * HW;
    float* ob = out + img * HW;
    bool hasL = (warp > 0), hasR = (warp < NW - 1);
    int wl = hasL ? warp - 1 : 0;
    int wr = hasR ? warp + 1 : NW - 1;

    float V[2][4];
    #pragma unroll
    for (int ser = 0; ser < 2; ser++)
        #pragma unroll
        for (int j = 0; j < 4; j++) V[ser][j] = 0.f;

    for (int r = max(0, s - RAD); r <= s + RAD; r++)
        addB<+1>(abr + r * W, col0, V);

    float inv_nx[4];
    #pragma unroll
    for (int j = 0; j < 4; j++) {
        int c = col0 + j;
        inv_nx[j] = __frcp_rn((float)(min(W - 1, c + RAD) - max(0, c - RAD) + 1));
    }

    for (int o = s; o < s + SEGR; o++) {
        int par = o & 1;
        pub_edges<2>(&sm[par][warp][0], lane, V);
        __syncthreads();

        float bx[2][4];
        #pragma unroll
        for (int ser = 0; ser < 2; ser++) {
            float4 L30 = sm[par][wl][2 * 2 + ser];
            float4 L31 = sm[par][wl][3 * 2 + ser];
            float4 R0  = sm[par][wr][0 * 2 + ser];
            float4 R1  = sm[par][wr][1 * 2 + ser];
            box4(V[ser], L30, L31, R0, R1, hasL, hasR, lane, bx[ser]);
        }

        float inv_ny = __frcp_rn((float)(min(Hh - 1, o + RAD) - max(0, o - RAD) + 1));
        float4 xv = *(const float4*)(xb + o * W + col0);
        float xs[4] = {xv.x, xv.y, xv.z, xv.w};
        float os[4];
        #pragma unroll
        for (int j = 0; j < 4; j++) {
            float invN = inv_nx[j] * inv_ny;
            os[j] = fmaf(bx[0][j] * invN, xs[j], bx[1][j] * invN);
        }
        float4 ov;
        ov.x = os[0]; ov.y = os[1]; ov.z = os[2]; ov.w = os[3];
        *(float4*)(ob + o * W + col0) = ov;

        int lead = o + RAD + 1, trail = o - RAD;
        if (lead < Hh)
            addB<+1>(abr + lead * W, col0, V);
        if (trail >= 0)
            addB<-1>(abr + trail * W, col0, V);
    }
}

extern "C" void kernel_launch(void* const* d_in, const int* in_sizes, int n_in,
                              void* d_out, int out_size) {
    const float* x = (const float*)d_in[0];
    const float* y = (const float*)d_in[1];
    float* out = (float*)d_out;

    dim3 grid(SEGS, IMGS);
    kA<<<grid, TPB>>>(x, y);
    kB<<<grid, TPB>>>(x, out);
}

// round 11
// speedup vs baseline: 1.5271x; 1.5271x over previous
#include <cuda_runtime.h>
#include <cuda_fp16.h>

// Guided filter, RADIUS=8, EPS=0.01, (8,3,1024,1024) fp32.
// kA (R8 config): horizontal-first, raw-value warp exchange, 24-wide register
//   window, 4 series local, SEGR_A=16; writes (a,b) packed half2.
// kB (R9 config): vertical-first running sums over half2 scratch, ONE
//   horizontal box per row via chain-free prefix identity + smem warp edges.

#define W     1024
#define Hh    1024
#define IMGS  24
#define HW    (Hh * W)
#define TOTAL (IMGS * HW)
#define RAD   8
#define EPSF  0.01f
#define SEGR_A 16
#define SEGS_A (Hh / SEGR_A)
#define SEGR_B 32
#define SEGS_B (Hh / SEGR_B)
#define TPB   128
#define NW    4
#define FULLM 0xffffffffu

__device__ __align__(16) __half2 g_ab[TOTAL];

__device__ __forceinline__ unsigned int pack_h2(float a, float b) {
    __half2 h = __floats2half2_rn(a, b);
    return *reinterpret_cast<unsigned int*>(&h);
}
__device__ __forceinline__ void dec_h2(unsigned int u, float& a, float& b) {
    __half2 h = *reinterpret_cast<__half2*>(&u);
    float2 f = __half22float2(h);
    a = f.x; b = f.y;
}

// ======================= kA (R8) ==========================================
__device__ __forceinline__ void load_strip(const float* __restrict__ r, int C,
                                           int lane, float v[8], float h[8]) {
    int col0 = C + lane * 8;
    float4 p0 = *(const float4*)(r + col0);
    float4 p1 = *(const float4*)(r + col0 + 4);
    v[0]=p0.x; v[1]=p0.y; v[2]=p0.z; v[3]=p0.w;
    v[4]=p1.x; v[5]=p1.y; v[6]=p1.z; v[7]=p1.w;
    #pragma unroll
    for (int j = 0; j < 8; j++) h[j] = 0.0f;
    if (lane == 0) {
        if (C > 0) {
            float4 a = *(const float4*)(r + C - 8);
            float4 b = *(const float4*)(r + C - 4);
            h[0]=a.x; h[1]=a.y; h[2]=a.z; h[3]=a.w;
            h[4]=b.x; h[5]=b.y; h[6]=b.z; h[7]=b.w;
        }
    } else if (lane == 31) {
        if (C + 256 < W) {
            float4 a = *(const float4*)(r + C + 256);
            float4 b = *(const float4*)(r + C + 260);
            h[0]=a.x; h[1]=a.y; h[2]=a.z; h[3]=a.w;
            h[4]=b.x; h[5]=b.y; h[6]=b.z; h[7]=b.w;
        }
    }
}

__device__ __forceinline__ void window24(const float v[8], const float h[8],
                                         int lane, float w[24]) {
    #pragma unroll
    for (int j = 0; j < 8; j++) w[8 + j] = v[j];
    #pragma unroll
    for (int j = 0; j < 8; j++) {
        float t = __shfl_up_sync(FULLM, v[j], 1);
        w[j] = (lane == 0) ? h[j] : t;
    }
    #pragma unroll
    for (int j = 0; j < 8; j++) {
        float t = __shfl_down_sync(FULLM, v[j], 1);
        w[16 + j] = (lane == 31) ? h[j] : t;
    }
}

template<int SGN>
__device__ __forceinline__ void visitA(const float* __restrict__ xr,
                                       const float* __restrict__ yr,
                                       int C, int lane,
                                       float s0[8], float s1[8],
                                       float s2[8], float s3[8]) {
    float vx[8], hx[8], vy[8], hy[8];
    load_strip(xr, C, lane, vx, hx);
    load_strip(yr, C, lane, vy, hy);
    float wx[24], wy[24];
    window24(vx, hx, lane, wx);
    window24(vy, hy, lane, wy);

    float sx = 0.f, sy = 0.f, sxx = 0.f, sxy = 0.f;
    #pragma unroll
    for (int j = 0; j < 17; j++) {
        float a = wx[j], b = wy[j];
        sx += a; sy += b;
        sxx = fmaf(a, a, sxx);
        sxy = fmaf(a, b, sxy);
    }
    #pragma unroll
    for (int k = 0; k < 8; k++) {
        if (k > 0) {
            float ao = wx[k-1], bo = wy[k-1];
            float an = wx[k+16], bn = wy[k+16];
            sx  += an - ao;
            sy  += bn - bo;
            sxx += an*an - ao*ao;
            sxy += an*bn - ao*bo;
        }
        if (SGN > 0) { s0[k] += sx; s1[k] += sy; s2[k] += sxx; s3[k] += sxy; }
        else         { s0[k] -= sx; s1[k] -= sy; s2[k] -= sxx; s3[k] -= sxy; }
    }
}

__global__ void __launch_bounds__(TPB) kA(const float* __restrict__ x,
                                          const float* __restrict__ y) {
    int img  = blockIdx.y;
    int s    = blockIdx.x * SEGR_A;
    int warp = threadIdx.x >> 5;
    int lane = threadIdx.x & 31;
    int C    = warp << 8;
    int col0 = C + lane * 8;
    const float* xb = x + img * HW;
    const float* yb = y + img * HW;

    float s0[8], s1[8], s2[8], s3[8];
    #pragma unroll
    for (int j = 0; j < 8; j++) { s0[j]=0.f; s1[j]=0.f; s2[j]=0.f; s3[j]=0.f; }

    for (int r = max(0, s - RAD); r <= s + RAD; r++)
        visitA<+1>(xb + r * W, yb + r * W, C, lane, s0, s1, s2, s3);

    float inv_nx[8];
    #pragma unroll
    for (int j = 0; j < 8; j++) {
        int c = col0 + j;
        inv_nx[j] = __frcp_rn((float)(min(W - 1, c + RAD) - max(0, c - RAD) + 1));
    }

    __half2* gab = g_ab + img * HW;

    for (int o = s; o < s + SEGR_A; o++) {
        float inv_ny = __frcp_rn((float)(min(Hh - 1, o + RAD) - max(0, o - RAD) + 1));
        unsigned int pk[8];
        #pragma unroll
        for (int j = 0; j < 8; j++) {
            float invN = inv_nx[j] * inv_ny;
            float mx = s0[j] * invN, my = s1[j] * invN;
            float varx = fmaf(-mx, mx, s2[j] * invN);
            float cov  = fmaf(-mx, my, s3[j] * invN);
            float a = __fdividef(cov, varx + EPSF);
            float b = fmaf(-a, mx, my);
            pk[j] = pack_h2(a, b);
        }
        uint4 u0, u1;
        u0.x = pk[0]; u0.y = pk[1]; u0.z = pk[2]; u0.w = pk[3];
        u1.x = pk[4]; u1.y = pk[5]; u1.z = pk[6]; u1.w = pk[7];
        *(uint4*)(gab + o * W + col0)     = u0;
        *(uint4*)(gab + o * W + col0 + 4) = u1;

        int lead = o + RAD + 1, trail = o - RAD;
        if (lead < Hh)
            visitA<+1>(xb + lead * W, yb + lead * W, C, lane, s0, s1, s2, s3);
        if (trail >= 0)
            visitA<-1>(xb + trail * W, yb + trail * W, C, lane, s0, s1, s2, s3);
    }
}

// ======================= kB (R9) ==========================================
__device__ __forceinline__ void boxV(const float V[8], const float hsuf[8],
                                     const float hpre[8], int lane, float bx[8]) {
    float p[9]; p[0] = 0.f;
    #pragma unroll
    for (int j = 0; j < 8; j++) p[j + 1] = p[j] + V[j];
    float U = p[8];
    float sufL[8], preR[8];
    #pragma unroll
    for (int j = 0; j < 8; j++) {
        float t = __shfl_up_sync(FULLM, U - p[j], 1);
        sufL[j] = (lane == 0) ? hsuf[j] : t;
    }
    #pragma unroll
    for (int j = 0; j < 8; j++) {
        float t = __shfl_down_sync(FULLM, p[j + 1], 1);
        preR[j] = (lane == 31) ? hpre[j] : t;
    }
    #pragma unroll
    for (int j = 0; j < 8; j++) bx[j] = (sufL[j] + U) + preR[j];
}

__device__ __forceinline__ void write_edges(const float V[8], float* pre_dst,
                                            float* suf_dst, int lane) {
    if (lane == 0) {
        float t[8]; float acc = 0.f;
        #pragma unroll
        for (int j = 0; j < 8; j++) { acc += V[j]; t[j] = acc; }
        *(float4*)(pre_dst)     = make_float4(t[0], t[1], t[2], t[3]);
        *(float4*)(pre_dst + 4) = make_float4(t[4], t[5], t[6], t[7]);
    } else if (lane == 31) {
        float t[8]; float acc = 0.f;
        #pragma unroll
        for (int j = 7; j >= 0; j--) { acc += V[j]; t[j] = acc; }
        *(float4*)(suf_dst)     = make_float4(t[0], t[1], t[2], t[3]);
        *(float4*)(suf_dst + 4) = make_float4(t[4], t[5], t[6], t[7]);
    }
}

__device__ __forceinline__ void get_halo(const float* sufsrc, const float* presrc,
                                         int warp, int lane,
                                         float hsuf[8], float hpre[8]) {
    #pragma unroll
    for (int j = 0; j < 8; j++) { hsuf[j] = 0.f; hpre[j] = 0.f; }
    if (lane == 0) {
        if (warp > 0) {
            float4 a = *(const float4*)sufsrc, b = *(const float4*)(sufsrc + 4);
            hsuf[0]=a.x; hsuf[1]=a.y; hsuf[2]=a.z; hsuf[3]=a.w;
            hsuf[4]=b.x; hsuf[5]=b.y; hsuf[6]=b.z; hsuf[7]=b.w;
        }
    } else if (lane == 31) {
        if (warp < NW - 1) {
            float4 a = *(const float4*)presrc, b = *(const float4*)(presrc + 4);
            hpre[0]=a.x; hpre[1]=a.y; hpre[2]=a.z; hpre[3]=a.w;
            hpre[4]=b.x; hpre[5]=b.y; hpre[6]=b.z; hpre[7]=b.w;
        }
    }
}

template<int SGN>
__device__ __forceinline__ void addB(const __half2* __restrict__ abr, int col0,
                                     float Va[8], float Vb[8]) {
    uint4 p0 = *(const uint4*)(abr + col0);
    uint4 p1 = *(const uint4*)(abr + col0 + 4);
    unsigned int u[8] = {p0.x,p0.y,p0.z,p0.w,p1.x,p1.y,p1.z,p1.w};
    #pragma unroll
    for (int j = 0; j < 8; j++) {
        float a, b; dec_h2(u[j], a, b);
        if (SGN > 0) { Va[j] += a; Vb[j] += b; }
        else         { Va[j] -= a; Vb[j] -= b; }
    }
}

__global__ void __launch_bounds__(TPB) kB(const float* __restrict__ x,
                                          float* __restrict__ out) {
    __shared__ __align__(16) float sm[2][NW][2][2][8];
    int img  = blockIdx.y;
    int s    = blockIdx.x * SEGR_B;
    int warp = threadIdx.x >> 5;
    int lane = threadIdx.x & 31;
    int col0 = (warp << 8) + lane * 8;
    const __half2* abr = g_ab + img * HW;
    const float* xb = x + img * HW;
    float* ob = out + img * HW;

    float Va[8], Vb[8];
    #pragma unroll
    for (int j = 0; j < 8; j++) { Va[j]=0.f; Vb[j]=0.f; }

    for (int r = max(0, s - RAD); r <= s + RAD; r++)
        addB<+1>(abr + r * W, col0, Va, Vb);

    float inv_nx[8];
    #pragma unroll
    for (int j = 0; j < 8; j++) {
        int c = col0 + j;
        inv_nx[j] = __frcp_rn((float)(min(W - 1, c + RAD) - max(0, c - RAD) + 1));
    }

    for (int o = s; o < s + SEGR_B; o++) {
        int par = o & 1;
        write_edges(Va, &sm[par][warp][0][0][0], &sm[par][warp][1][0][0], lane);
        write_edges(Vb, &sm[par][warp][0][1][0], &sm[par][warp][1][1][0], lane);
        __syncthreads();

        float bxa[8], bxb[8], hsuf[8], hpre[8];
        int wl = (warp > 0) ? warp - 1 : 0;
        int wr = (warp < NW - 1) ? warp + 1 : NW - 1;
        get_halo(&sm[par][wl][1][0][0], &sm[par][wr][0][0][0], warp, lane, hsuf, hpre);
        boxV(Va, hsuf, hpre, lane, bxa);
        get_halo(&sm[par][wl][1][1][0], &sm[par][wr][0][1][0], warp, lane, hsuf, hpre);
        boxV(Vb, hsuf, hpre, lane, bxb);

        float inv_ny = __frcp_rn((float)(min(Hh - 1, o + RAD) - max(0, o - RAD) + 1));
        float4 x0 = *(const float4*)(xb + o * W + col0);
        float4 x1 = *(const float4*)(xb + o * W + col0 + 4);
        float xs[8] = {x0.x,x0.y,x0.z,x0.w,x1.x,x1.y,x1.z,x1.w};
        float os[8];
        #pragma unroll
        for (int j = 0; j < 8; j++) {
            float invN = inv_nx[j] * inv_ny;
            os[j] = fmaf(bxa[j] * invN, xs[j], bxb[j] * invN);
        }
        float4 o0, o1;
        o0.x = os[0]; o0.y = os[1]; o0.z = os[2]; o0.w = os[3];
        o1.x = os[4]; o1.y = os[5]; o1.z = os[6]; o1.w = os[7];
        *(float4*)(ob + o * W + col0)     = o0;
        *(float4*)(ob + o * W + col0 + 4) = o1;

        int lead = o + RAD + 1, trail = o - RAD;
        if (lead < Hh)
            addB<+1>(abr + lead * W, col0, Va, Vb);
        if (trail >= 0)
            addB<-1>(abr + trail * W, col0, Va, Vb);
    }
}

extern "C" void kernel_launch(void* const* d_in, const int* in_sizes, int n_in,
                              void* d_out, int out_size) {
    const float* x = (const float*)d_in[0];
    const float* y = (const float*)d_in[1];
    float* out = (float*)d_out;

    dim3 gridA(SEGS_A, IMGS);
    dim3 gridB(SEGS_B, IMGS);
    kA<<<gridA, TPB>>>(x, y);
    kB<<<gridB, TPB>>>(x, out);
}

// round 12
// speedup vs baseline: 1.5669x; 1.0261x over previous
#include <cuda_runtime.h>
#include <cuda_fp16.h>

// Guided filter, RADIUS=8, EPS=0.01, (8,3,1024,1024) fp32 — FULLY FUSED.
// One block = full 1024-col width (4 warps x 8 cols/lane), marches SEGR rows.
// Production cursor q=o+8: vertical sums of {x,y,xx,xy} -> 4-series h-box ->
// (a,b) packed half2 into a 17-row smem ring (per-thread private slots).
// Output cursor o: Va/Vb running sums (add decoded regs, sub ring) ->
// 2-series h-box -> out = A*x + B.

#define W     1024
#define Hh    1024
#define IMGS  24
#define HW    (Hh * W)
#define RAD   8
#define EPSF  0.01f
#define SEGR  64
#define SEGS  (Hh / SEGR)
#define TPB   128
#define NW    4
#define FULLM 0xffffffffu

#define RING_U (17 * 1024)
#define EX_F   (2 * NW * 2 * 4 * 8)   // parity, warp, side, series, 8
#define EAB_F  (2 * NW * 2 * 2 * 8)
#define SMEM_BYTES (RING_U * 4 + (EX_F + EAB_F) * 4)   // 72704

__device__ __forceinline__ unsigned int pack_h2(float a, float b) {
    __half2 h = __floats2half2_rn(a, b);
    return *reinterpret_cast<unsigned int*>(&h);
}
__device__ __forceinline__ void dec_h2(unsigned int u, float& a, float& b) {
    __half2 h = *reinterpret_cast<__half2*>(&u);
    float2 f = __half22float2(h);
    a = f.x; b = f.y;
}

// 17-wide horizontal box of per-lane vertical sums V[8] (chain-free).
__device__ __forceinline__ void boxV(const float V[8], const float hsuf[8],
                                     const float hpre[8], int lane, float bx[8]) {
    float p[9]; p[0] = 0.f;
    #pragma unroll
    for (int j = 0; j < 8; j++) p[j + 1] = p[j] + V[j];
    float U = p[8];
    float sufL[8], preR[8];
    #pragma unroll
    for (int j = 0; j < 8; j++) {
        float t = __shfl_up_sync(FULLM, U - p[j], 1);
        sufL[j] = (lane == 0) ? hsuf[j] : t;
    }
    #pragma unroll
    for (int j = 0; j < 8; j++) {
        float t = __shfl_down_sync(FULLM, p[j + 1], 1);
        preR[j] = (lane == 31) ? hpre[j] : t;
    }
    #pragma unroll
    for (int j = 0; j < 8; j++) bx[j] = (sufL[j] + U) + preR[j];
}

__device__ __forceinline__ void write_edges(const float V[8], float* pre_dst,
                                            float* suf_dst, int lane) {
    if (lane == 0) {
        float t[8]; float acc = 0.f;
        #pragma unroll
        for (int j = 0; j < 8; j++) { acc += V[j]; t[j] = acc; }
        *(float4*)(pre_dst)     = make_float4(t[0], t[1], t[2], t[3]);
        *(float4*)(pre_dst + 4) = make_float4(t[4], t[5], t[6], t[7]);
    } else if (lane == 31) {
        float t[8]; float acc = 0.f;
        #pragma unroll
        for (int j = 7; j >= 0; j--) { acc += V[j]; t[j] = acc; }
        *(float4*)(suf_dst)     = make_float4(t[0], t[1], t[2], t[3]);
        *(float4*)(suf_dst + 4) = make_float4(t[4], t[5], t[6], t[7]);
    }
}

__device__ __forceinline__ void get_halo(const float* sufsrc, const float* presrc,
                                         int warp, int lane,
                                         float hsuf[8], float hpre[8]) {
    #pragma unroll
    for (int j = 0; j < 8; j++) { hsuf[j] = 0.f; hpre[j] = 0.f; }
    if (lane == 0) {
        if (warp > 0) {
            float4 a = *(const float4*)sufsrc, b = *(const float4*)(sufsrc + 4);
            hsuf[0]=a.x; hsuf[1]=a.y; hsuf[2]=a.z; hsuf[3]=a.w;
            hsuf[4]=b.x; hsuf[5]=b.y; hsuf[6]=b.z; hsuf[7]=b.w;
        }
    } else if (lane == 31) {
        if (warp < NW - 1) {
            float4 a = *(const float4*)presrc, b = *(const float4*)(presrc + 4);
            hpre[0]=a.x; hpre[1]=a.y; hpre[2]=a.z; hpre[3]=a.w;
            hpre[4]=b.x; hpre[5]=b.y; hpre[6]=b.z; hpre[7]=b.w;
        }
    }
}

template<int SGN>
__device__ __forceinline__ void addXY(const float* __restrict__ xr,
                                      const float* __restrict__ yr, int col0,
                                      float VX[8], float VY[8],
                                      float VXX[8], float VXY[8]) {
    float4 a0 = *(const float4*)(xr + col0), a1 = *(const float4*)(xr + col0 + 4);
    float4 b0 = *(const float4*)(yr + col0), b1 = *(const float4*)(yr + col0 + 4);
    float xv[8] = {a0.x,a0.y,a0.z,a0.w,a1.x,a1.y,a1.z,a1.w};
    float yv[8] = {b0.x,b0.y,b0.z,b0.w,b1.x,b1.y,b1.z,b1.w};
    #pragma unroll
    for (int j = 0; j < 8; j++) {
        if (SGN > 0) {
            VX[j] += xv[j]; VY[j] += yv[j];
            VXX[j] = fmaf(xv[j], xv[j], VXX[j]);
            VXY[j] = fmaf(xv[j], yv[j], VXY[j]);
        } else {
            VX[j] -= xv[j]; VY[j] -= yv[j];
            VXX[j] = fmaf(-xv[j], xv[j], VXX[j]);
            VXY[j] = fmaf(-xv[j], yv[j], VXY[j]);
        }
    }
}

__global__ void __launch_bounds__(TPB) kF(const float* __restrict__ x,
                                          const float* __restrict__ y,
                                          float* __restrict__ out) {
    extern __shared__ __align__(16) char smraw[];
    unsigned int* ring = (unsigned int*)smraw;          // [17][1024]
    float* eX  = (float*)(smraw + RING_U * 4);          // [2][NW][2][4][8]
    float* eAB = eX + EX_F;                             // [2][NW][2][2][8]

    int img  = blockIdx.y;
    int s    = blockIdx.x * SEGR;
    int warp = threadIdx.x >> 5;
    int lane = threadIdx.x & 31;
    int col0 = (warp << 8) + lane * 8;
    const float* xb = x + img * HW;
    const float* yb = y + img * HW;
    float* ob = out + img * HW;
    int wl = (warp > 0) ? warp - 1 : 0;
    int wr = (warp < NW - 1) ? warp + 1 : NW - 1;

    float VX[8], VY[8], VXX[8], VXY[8], Va[8], Vb[8];
    #pragma unroll
    for (int j = 0; j < 8; j++) {
        VX[j]=0.f; VY[j]=0.f; VXX[j]=0.f; VXY[j]=0.f; Va[j]=0.f; Vb[j]=0.f;
    }

    // init production window for q0 = s-8: rows [max(0, s-16), s]
    for (int r = max(0, s - 16); r <= s; r++)
        addXY<+1>(xb + r * W, yb + r * W, col0, VX, VY, VXX, VXY);

    float inv_nx[8];
    #pragma unroll
    for (int j = 0; j < 8; j++) {
        int c = col0 + j;
        inv_nx[j] = __frcp_rn((float)(min(W - 1, c + RAD) - max(0, c - RAD) + 1));
    }

    // produce a-row q: 4-series h-box of VX..VXY, epilogue, pack+ring+Va add.
    auto produce = [&](int q) {
        float* eXp = eX + (q & 1) * (NW * 2 * 4 * 8);
        write_edges(VX,  eXp + warp*64 +  0, eXp + warp*64 + 32, lane);
        write_edges(VY,  eXp + warp*64 +  8, eXp + warp*64 + 40, lane);
        write_edges(VXX, eXp + warp*64 + 16, eXp + warp*64 + 48, lane);
        write_edges(VXY, eXp + warp*64 + 24, eXp + warp*64 + 56, lane);
        __syncthreads();
        float bx0[8], bx1[8], bx2[8], bx3[8], hsuf[8], hpre[8];
        get_halo(eXp + wl*64 + 32, eXp + wr*64 +  0, warp, lane, hsuf, hpre);
        boxV(VX,  hsuf, hpre, lane, bx0);
        get_halo(eXp + wl*64 + 40, eXp + wr*64 +  8, warp, lane, hsuf, hpre);
        boxV(VY,  hsuf, hpre, lane, bx1);
        get_halo(eXp + wl*64 + 48, eXp + wr*64 + 16, warp, lane, hsuf, hpre);
        boxV(VXX, hsuf, hpre, lane, bx2);
        get_halo(eXp + wl*64 + 56, eXp + wr*64 + 24, warp, lane, hsuf, hpre);
        boxV(VXY, hsuf, hpre, lane, bx3);

        float inv_ny = __frcp_rn((float)(min(Hh - 1, q + RAD) - max(0, q - RAD) + 1));
        unsigned int pk[8];
        #pragma unroll
        for (int j = 0; j < 8; j++) {
            float invN = inv_nx[j] * inv_ny;
            float mx = bx0[j] * invN, my = bx1[j] * invN;
            float varx = fmaf(-mx, mx, bx2[j] * invN);
            float cov  = fmaf(-mx, my, bx3[j] * invN);
            float a = __fdividef(cov, varx + EPSF);
            float b = fmaf(-a, mx, my);
            unsigned int u = pack_h2(a, b);
            pk[j] = u;
            float ad, bd; dec_h2(u, ad, bd);
            Va[j] += ad; Vb[j] += bd;
        }
        unsigned int* rp = ring + (q % 17) * 1024 + col0;
        *(uint4*)rp       = make_uint4(pk[0], pk[1], pk[2], pk[3]);
        *(uint4*)(rp + 4) = make_uint4(pk[4], pk[5], pk[6], pk[7]);
    };

    // warm-up: produce a-rows q = s-8 .. s+7 (clipped)
    for (int q = s - 8; q < s + 8; q++) {
        if (q >= 0) produce(q);
        int lead = q + 9;
        if (lead <= Hh - 1)
            addXY<+1>(xb + lead * W, yb + lead * W, col0, VX, VY, VXX, VXY);
        int tr = q - 8;
        if (tr >= 0)
            addXY<-1>(xb + tr * W, yb + tr * W, col0, VX, VY, VXX, VXY);
    }

    // main loop
    for (int o = s; o < s + SEGR; o++) {
        int q = o + 8;
        bool prod = (q <= Hh - 1);          // uniform per block

        // trail subtract FIRST (slot q%17 still holds row q-17 = o-9)
        int t = o - 9;
        if (t >= 0 && t >= s - 8) {
            const unsigned int* rp = ring + (t % 17) * 1024 + col0;
            uint4 u0 = *(const uint4*)rp, u1 = *(const uint4*)(rp + 4);
            unsigned int uu[8] = {u0.x,u0.y,u0.z,u0.w,u1.x,u1.y,u1.z,u1.w};
            #pragma unroll
            for (int j = 0; j < 8; j++) {
                float ad, bd; dec_h2(uu[j], ad, bd);
                Va[j] -= ad; Vb[j] -= bd;
            }
        }

        if (prod) produce(q);

        float* eABp = eAB + (o & 1) * (NW * 2 * 2 * 8);
        write_edges(Va, eABp + warp*32 + 0, eABp + warp*32 + 16, lane);
        write_edges(Vb, eABp + warp*32 + 8, eABp + warp*32 + 24, lane);
        __syncthreads();

        float bxa[8], bxb[8], hsuf[8], hpre[8];
        get_halo(eABp + wl*32 + 16, eABp + wr*32 + 0, warp, lane, hsuf, hpre);
        boxV(Va, hsuf, hpre, lane, bxa);
        get_halo(eABp + wl*32 + 24, eABp + wr*32 + 8, warp, lane, hsuf, hpre);
        boxV(Vb, hsuf, hpre, lane, bxb);

        float inv_ny = __frcp_rn((float)(min(Hh - 1, o + RAD) - max(0, o - RAD) + 1));
        float4 x0 = *(const float4*)(xb + o * W + col0);
        float4 x1 = *(const float4*)(xb + o * W + col0 + 4);
        float xs[8] = {x0.x,x0.y,x0.z,x0.w,x1.x,x1.y,x1.z,x1.w};
        float os[8];
        #pragma unroll
        for (int j = 0; j < 8; j++) {
            float invN = inv_nx[j] * inv_ny;
            os[j] = fmaf(bxa[j] * invN, xs[j], bxb[j] * invN);
        }
        *(float4*)(ob + o * W + col0)     = make_float4(os[0], os[1], os[2], os[3]);
        *(float4*)(ob + o * W + col0 + 4) = make_float4(os[4], os[5], os[6], os[7]);

        // advance production window (reuse xs for the x trail subtract)
        if (prod) {
            int lead = q + 9;
            if (lead <= Hh - 1)
                addXY<+1>(xb + lead * W, yb + lead * W, col0, VX, VY, VXX, VXY);
            float4 y0 = *(const float4*)(yb + o * W + col0);
            float4 y1 = *(const float4*)(yb + o * W + col0 + 4);
            float ys[8] = {y0.x,y0.y,y0.z,y0.w,y1.x,y1.y,y1.z,y1.w};
            #pragma unroll
            for (int j = 0; j < 8; j++) {
                VX[j] -= xs[j]; VY[j] -= ys[j];
                VXX[j] = fmaf(-xs[j], xs[j], VXX[j]);
                VXY[j] = fmaf(-xs[j], ys[j], VXY[j]);
            }
        }
    }
}

extern "C" void kernel_launch(void* const* d_in, const int* in_sizes, int n_in,
                              void* d_out, int out_size) {
    const float* x = (const float*)d_in[0];
    const float* y = (const float*)d_in[1];
    float* out = (float*)d_out;

    cudaFuncSetAttribute(kF, cudaFuncAttributeMaxDynamicSharedMemorySize,
                         SMEM_BYTES);
    dim3 grid(SEGS, IMGS);
    kF<<<grid, TPB, SMEM_BYTES>>>(x, y, out);
}